// round 15
// baseline (speedup 1.0000x reference)
#include <cuda_runtime.h>
#include <math.h>

#define N_MASKS  256
#define S_COARSE 37632
#define K_SEL    9408
#define F_FINE   3136
#define P_TOT    12544
#define SRC_HW   256
#define TGT_HW   512
#define CHUNKS   4
#define S_CHUNK  (S_COARSE / CHUNKS)   // 9408
#define F_CHUNK  (F_FINE / CHUNKS)     // 784

// k_coarse tiling
#define HALF_ROWS   129
#define TILE_FLOATS (HALF_ROWS * SRC_HW)          // 129 KB
#define TILE_BYTES  (TILE_FLOATS * 4)
#define HIST_BINS   2048
#define COARSE_SMEM (TILE_BYTES + HIST_BINS * 4)  // 137 KB
#define CSPLIT      2
#define M_SPLIT     (S_COARSE / CSPLIT)           // 18816

// k_gather tiling
#define SLICES      8
#define SLICE_ROWS  64
#define GROWS       65                            // 64 owned rows + 1 halo
#define GATHER_SMEM (GROWS * TGT_HW * 4)          // 133120 B

// ---------------- scratch (no cudaMalloc allowed) ----------------
__device__ float        g_logits[N_MASKS * S_COARSE];          // ~38.5 MB
__device__ unsigned int g_hist[N_MASKS * HIST_BINS];           // 2 MB, zeroed per call
__device__ unsigned int g_T22[N_MASKS];
__device__ unsigned int g_below[N_MASKS];
__device__ unsigned int g_eqpref[N_MASKS * CHUNKS];
__device__ unsigned int g_selbase[N_MASKS * CHUNKS];
__device__ float2       g_px[N_MASKS * P_TOT];                 // ~25.7 MB compacted coords
__device__ float        g_pl[N_MASKS * P_TOT];                 // ~12.8 MB compacted logits
__device__ float        g_row[N_MASKS * SLICES * 4];

// ---- global-memory bilinear (fine src), matches grid_sample(zeros, ac=False) ----
__device__ __forceinline__ float bilin(const float* __restrict__ img, int HW,
                                       float cx, float cy) {
    float x = cx * (float)HW - 0.5f;
    float y = cy * (float)HW - 0.5f;
    float x0f = floorf(x), y0f = floorf(y);
    int x0 = (int)x0f, y0 = (int)y0f;
    float wx = x - x0f, wy = y - y0f;
    int x1 = x0 + 1, y1 = y0 + 1;
    bool vx0 = (x0 >= 0) & (x0 < HW);
    bool vx1 = (x1 >= 0) & (x1 < HW);
    bool vy0 = (y0 >= 0) & (y0 < HW);
    bool vy1 = (y1 >= 0) & (y1 < HW);
    float v00 = (vx0 && vy0) ? __ldg(img + y0 * HW + x0) : 0.0f;
    float v01 = (vx1 && vy0) ? __ldg(img + y0 * HW + x1) : 0.0f;
    float v10 = (vx0 && vy1) ? __ldg(img + y1 * HW + x0) : 0.0f;
    float v11 = (vx1 && vy1) ? __ldg(img + y1 * HW + x1) : 0.0f;
    return v00 * (1.0f - wx) * (1.0f - wy) + v01 * wx * (1.0f - wy)
         + v10 * (1.0f - wx) * wy          + v11 * wx * wy;
}

// ------- K1: coarse logits via smem-tiled src image + fused pass-1 histogram -------
__global__ __launch_bounds__(1024)
void k_coarse(const float* __restrict__ src, const float* __restrict__ rc) {
    extern __shared__ float sm[];
    unsigned int* hist = (unsigned int*)(sm + TILE_FLOATS);
    int n = blockIdx.y;
    int half  = blockIdx.x & 1;
    int split = blockIdx.x >> 1;
    int base_row = half * 128;
    int nrows = half ? 128 : 129;

    hist[threadIdx.x] = 0;
    hist[threadIdx.x + 1024] = 0;

    const float4* img4 = (const float4*)(src + (size_t)n * (SRC_HW * SRC_HW)
                                         + base_row * SRC_HW);
    int nf4 = nrows * (SRC_HW / 4);
    for (int i = threadIdx.x; i < nf4; i += 1024)
        ((float4*)sm)[i] = img4[i];
    __syncthreads();

    const float4* rc4 = (const float4*)((const float2*)rc
                         + (size_t)n * S_COARSE + split * M_SPLIT);
    float* lrow = g_logits + (size_t)n * S_COARSE + split * M_SPLIT;

    for (int s = threadIdx.x * 4; s < M_SPLIT; s += 4096) {
        float4 a = __ldg(rc4 + (s >> 1));
        float4 b = __ldg(rc4 + (s >> 1) + 1);
        float cxs[4] = {a.x, a.z, b.x, b.z};
        float cys[4] = {a.y, a.w, b.y, b.w};
        #pragma unroll
        for (int p = 0; p < 4; p++) {
            float x = cxs[p] * (float)SRC_HW - 0.5f;
            float y = cys[p] * (float)SRC_HW - 0.5f;
            float x0f = floorf(x), y0f = floorf(y);
            int x0 = (int)x0f, y0 = (int)y0f;
            bool owned = half ? (y0 >= 128) : (y0 <= 127);
            if (!owned) continue;
            float wx = x - x0f, wy = y - y0f;
            int x1 = x0 + 1, y1 = y0 + 1;
            int ly0 = y0 - base_row, ly1 = y1 - base_row;
            bool vx0 = (x0 >= 0) & (x0 < SRC_HW);
            bool vx1 = (x1 >= 0) & (x1 < SRC_HW);
            bool vy0 = (y0 >= 0) & (y0 < SRC_HW);
            bool vy1 = (y1 >= 0) & (y1 < SRC_HW);
            int cx0 = min(max(x0, 0), SRC_HW - 1);
            int cx1 = min(max(x1, 0), SRC_HW - 1);
            int cy0 = min(max(ly0, 0), nrows - 1);
            int cy1 = min(max(ly1, 0), nrows - 1);
            float v00 = (vx0 && vy0) ? sm[cy0 * SRC_HW + cx0] : 0.0f;
            float v01 = (vx1 && vy0) ? sm[cy0 * SRC_HW + cx1] : 0.0f;
            float v10 = (vx0 && vy1) ? sm[cy1 * SRC_HW + cx0] : 0.0f;
            float v11 = (vx1 && vy1) ? sm[cy1 * SRC_HW + cx1] : 0.0f;
            float val = v00 * (1.0f - wx) * (1.0f - wy) + v01 * wx * (1.0f - wy)
                      + v10 * (1.0f - wx) * wy          + v11 * wx * wy;
            lrow[s + p] = val;
            atomicAdd(&hist[(__float_as_uint(val) & 0x7fffffffu) >> 21], 1u);
        }
    }

    __syncthreads();
    unsigned int* gh = g_hist + (size_t)n * HIST_BINS;
    #pragma unroll
    for (int k = 0; k < 2; k++) {
        int i = threadIdx.x + k * 1024;
        unsigned int c = hist[i];
        if (c) atomicAdd(&gh[i], c);
    }
}

// ---- K2: select from g_hist + refine + per-chunk lt/eq counts -> selbase ----
__global__ __launch_bounds__(1024)
void k_select() {
    __shared__ unsigned int h[2048];
    __shared__ unsigned int ps[1024];
    __shared__ unsigned int s_b1, s_cum1, s_T, s_below;
    __shared__ unsigned int s_eq[CHUNKS], s_lt[CHUNKS];
    int n = blockIdx.x, t = threadIdx.x;
    const float* row = g_logits + (size_t)n * S_COARSE;

    // ---- pass 1: precomputed histogram ----
    const unsigned int* gh = g_hist + (size_t)n * HIST_BINS;
    h[t] = gh[t]; h[t + 1024] = gh[t + 1024];
    __syncthreads();
    unsigned int my = h[2 * t] + h[2 * t + 1];
    ps[t] = my;
    __syncthreads();
    for (int off = 1; off < 1024; off <<= 1) {
        unsigned int v = (t >= off) ? ps[t - off] : 0u;
        __syncthreads();
        ps[t] += v;
        __syncthreads();
    }
    {
        unsigned int excl = ps[t] - my;
        unsigned int c0 = excl,       h0 = h[2 * t];
        unsigned int c1 = excl + h0,  h1 = h[2 * t + 1];
        if (c0 < K_SEL && c0 + h0 >= K_SEL) { s_b1 = 2 * t;     s_cum1 = c0; }
        if (c1 < K_SEL && c1 + h1 >= K_SEL) { s_b1 = 2 * t + 1; s_cum1 = c1; }
    }
    __syncthreads();
    unsigned int b1 = s_b1, base = s_cum1;

    // ---- pass 2: refine next 11 bits ----
    h[t] = 0; h[t + 1024] = 0;
    __syncthreads();
    for (int s = t; s < S_COARSE; s += 1024) {
        unsigned int bits = __float_as_uint(row[s]) & 0x7fffffffu;
        if ((bits >> 21) == b1) atomicAdd(&h[(bits >> 10) & 0x7ffu], 1u);
    }
    __syncthreads();
    my = h[2 * t] + h[2 * t + 1];
    ps[t] = my;
    __syncthreads();
    for (int off = 1; off < 1024; off <<= 1) {
        unsigned int v = (t >= off) ? ps[t - off] : 0u;
        __syncthreads();
        ps[t] += v;
        __syncthreads();
    }
    {
        unsigned int excl = ps[t] - my;
        unsigned int c0 = base + excl,      h0 = h[2 * t];
        unsigned int c1 = base + excl + h0, h1 = h[2 * t + 1];
        if (c0 < K_SEL && c0 + h0 >= K_SEL) { s_T = (b1 << 11) | (2u * t);      s_below = c0; }
        if (c1 < K_SEL && c1 + h1 >= K_SEL) { s_T = (b1 << 11) | (2u * t + 1u); s_below = c1; }
    }
    if (t < CHUNKS) { s_eq[t] = 0; s_lt[t] = 0; }
    __syncthreads();
    unsigned int T = s_T;

    // ---- pass 3: per-chunk lt/eq counts ----
    for (int s = t; s < S_COARSE; s += 1024) {
        unsigned int b22 = (__float_as_uint(row[s]) & 0x7fffffffu) >> 10;
        if (b22 < T)       atomicAdd(&s_lt[s / S_CHUNK], 1u);
        else if (b22 == T) atomicAdd(&s_eq[s / S_CHUNK], 1u);
    }
    __syncthreads();
    if (t == 0) {
        g_T22[n] = T;
        g_below[n] = s_below;
        unsigned int r = K_SEL - s_below;
        unsigned int eqrun = 0, selrun = 0;
        #pragma unroll
        for (int c = 0; c < CHUNKS; c++) {
            g_eqpref[n * CHUNKS + c]  = eqrun;
            g_selbase[n * CHUNKS + c] = selrun;
            unsigned int take = (r > eqrun) ? min(r - eqrun, s_eq[c]) : 0u;
            selrun += s_lt[c] + take;
            eqrun  += s_eq[c];
        }
    }
}

// ---- K3a: deterministic compaction of selected (coord, logit). grid (CHUNKS,N) ----
__global__ __launch_bounds__(256)
void k_compact(const float* __restrict__ src,
               const float* __restrict__ rc, const float* __restrict__ rf) {
    int chunk = blockIdx.x, n = blockIdx.y, t = threadIdx.x;
    int lane = t & 31, wid = t >> 5;
    unsigned int T = g_T22[n];
    unsigned int r = K_SEL - g_below[n];
    unsigned int run_eq  = g_eqpref[n * CHUNKS + chunk];
    unsigned int run_sel = g_selbase[n * CHUNKS + chunk];
    unsigned int lanemask = (1u << lane) - 1u;

    __shared__ unsigned int wc_eq[8], wc_sel[8];

    const float*  lrow = g_logits + (size_t)n * S_COARSE;
    const float2* rc2  = (const float2*)rc + (size_t)n * S_COARSE;
    float2* px = g_px + (size_t)n * P_TOT;
    float*  pl = g_pl + (size_t)n * P_TOT;

    int s_begin = chunk * S_CHUNK, s_end = s_begin + S_CHUNK;
    for (int base = s_begin; base < s_end; base += 256) {
        int s = base + t;
        bool valid = s < s_end;
        float logit = 0.0f;
        unsigned int b22 = 0xffffffffu;
        if (valid) {
            logit = lrow[s];
            b22 = (__float_as_uint(logit) & 0x7fffffffu) >> 10;
        }
        bool lt = valid && (b22 < T);
        bool eq = valid && (b22 == T);
        unsigned int bal_eq = __ballot_sync(0xffffffffu, eq);
        if (lane == 0) wc_eq[wid] = (unsigned int)__popc(bal_eq);
        __syncthreads();
        unsigned int wb_eq = 0, etot = 0;
        #pragma unroll
        for (int w = 0; w < 8; w++) {
            unsigned int c = wc_eq[w];
            wb_eq += (w < wid) ? c : 0u;
            etot  += c;
        }
        unsigned int rank = run_eq + wb_eq + (unsigned int)__popc(bal_eq & lanemask);
        bool sel = lt || (eq && rank < r);

        unsigned int bal_sel = __ballot_sync(0xffffffffu, sel);
        if (lane == 0) wc_sel[wid] = (unsigned int)__popc(bal_sel);
        __syncthreads();
        unsigned int wb_sel = 0, stot = 0;
        #pragma unroll
        for (int w = 0; w < 8; w++) {
            unsigned int c = wc_sel[w];
            wb_sel += (w < wid) ? c : 0u;
            stot   += c;
        }
        if (sel) {
            unsigned int off = run_sel + wb_sel + (unsigned int)__popc(bal_sel & lanemask);
            px[off] = rc2[s];
            pl[off] = logit;
        }
        run_eq  += etot;
        run_sel += stot;
        __syncthreads();
    }

    // fine points: logit from src (global bilin), appended after K_SEL
    const float* simg = src + (size_t)n * (SRC_HW * SRC_HW);
    const float2* rf2 = (const float2*)rf + (size_t)n * F_FINE;
    int f_begin = chunk * F_CHUNK, f_end = f_begin + F_CHUNK;
    for (int f = f_begin + t; f < f_end; f += 256) {
        float2 c = rf2[f];
        px[K_SEL + f] = c;
        pl[K_SEL + f] = bilin(simg, SRC_HW, c.x, c.y);
    }
}

// ---------------- per-point loss accumulation ----------------
__device__ __forceinline__ void acc_point(float logit, float label,
                                          float& a_bce, float& a_pl, float& a_p, float& a_l) {
    float e = expf(-fabsf(logit));
    float prob = (logit >= 0.0f) ? 1.0f / (1.0f + e) : e / (1.0f + e);
    float bce  = fmaxf(logit, 0.0f) - logit * label + log1pf(e);
    a_bce += bce;
    a_pl  += prob * label;
    a_p   += prob;
    a_l   += label;
}

// ---- K3b: smem-tiled tgt gather + loss. grid (SLICES, N_MASKS), 512 thr ----
__global__ __launch_bounds__(512)
void k_gather(const float* __restrict__ tgt) {
    extern __shared__ float sm[];
    int slice = blockIdx.x, n = blockIdx.y, t = threadIdx.x;
    int lane = t & 31, wid = t >> 5;
    int base = slice * SLICE_ROWS;
    int nrows = (slice == SLICES - 1) ? 64 : 65;

    // dense fill of tgt slice
    const float4* timg4 = (const float4*)(tgt + (size_t)n * (TGT_HW * TGT_HW)
                                          + base * TGT_HW);
    int nf4 = nrows * (TGT_HW / 4);
    for (int i = t; i < nf4; i += 512)
        ((float4*)sm)[i] = timg4[i];
    __syncthreads();

    const float2* px = g_px + (size_t)n * P_TOT;
    const float*  pl = g_pl + (size_t)n * P_TOT;

    float a_bce = 0.f, a_pl = 0.f, a_p = 0.f, a_l = 0.f;

    for (int i = t; i < P_TOT; i += 512) {
        float2 c = px[i];
        float y = c.y * (float)TGT_HW - 0.5f;
        float y0f = floorf(y);
        int y0 = (int)y0f;
        int own = min(max(y0, 0), TGT_HW - 1) >> 6;
        if (own != slice) continue;
        float x = c.x * (float)TGT_HW - 0.5f;
        float x0f = floorf(x);
        int x0 = (int)x0f;
        float wx = x - x0f, wy = y - y0f;
        int x1 = x0 + 1, y1 = y0 + 1;
        int ly0 = y0 - base, ly1 = y1 - base;
        bool vx0 = (x0 >= 0) & (x0 < TGT_HW);
        bool vx1 = (x1 >= 0) & (x1 < TGT_HW);
        bool vy0 = (y0 >= 0) & (y0 < TGT_HW);
        bool vy1 = (y1 >= 0) & (y1 < TGT_HW);
        int cx0 = min(max(x0, 0), TGT_HW - 1);
        int cx1 = min(max(x1, 0), TGT_HW - 1);
        int cy0 = min(max(ly0, 0), nrows - 1);
        int cy1 = min(max(ly1, 0), nrows - 1);
        float v00 = (vx0 && vy0) ? sm[cy0 * TGT_HW + cx0] : 0.0f;
        float v01 = (vx1 && vy0) ? sm[cy0 * TGT_HW + cx1] : 0.0f;
        float v10 = (vx0 && vy1) ? sm[cy1 * TGT_HW + cx0] : 0.0f;
        float v11 = (vx1 && vy1) ? sm[cy1 * TGT_HW + cx1] : 0.0f;
        float label = v00 * (1.0f - wx) * (1.0f - wy) + v01 * wx * (1.0f - wy)
                    + v10 * (1.0f - wx) * wy          + v11 * wx * wy;
        acc_point(pl[i], label, a_bce, a_pl, a_p, a_l);
    }

    // deterministic block reduction (16 warps)
    __shared__ float red[16];
    __syncthreads();
    float vals[4] = {a_bce, a_pl, a_p, a_l};
    #pragma unroll
    for (int k = 0; k < 4; k++) {
        float v = vals[k];
        #pragma unroll
        for (int o = 16; o > 0; o >>= 1) v += __shfl_down_sync(0xffffffffu, v, o);
        if (lane == 0) red[wid] = v;
        __syncthreads();
        if (t == 0) {
            float tot = 0.f;
            #pragma unroll
            for (int w = 0; w < 16; w++) tot += red[w];
            g_row[(n * SLICES + slice) * 4 + k] = tot;
        }
        __syncthreads();
    }
}

// ---------------- K4: final reduction -> 2 outputs ----------------
__global__ __launch_bounds__(256)
void k_final(float* __restrict__ out) {
    __shared__ float s_ce[256];
    __shared__ float s_d[256];
    int t = threadIdx.x;           // t = row
    float bce = 0.f, pl = 0.f, p = 0.f, l = 0.f;
    #pragma unroll
    for (int c = 0; c < SLICES; c++) {
        const float* g = &g_row[(t * SLICES + c) * 4];
        bce += g[0]; pl += g[1]; p += g[2]; l += g[3];
    }
    s_ce[t] = bce / (float)P_TOT;
    s_d[t]  = 1.0f - (2.0f * pl + 1.0f) / (p + l + 1.0f);
    __syncthreads();
    for (int o = 128; o > 0; o >>= 1) {
        if (t < o) { s_ce[t] += s_ce[t + o]; s_d[t] += s_d[t + o]; }
        __syncthreads();
    }
    if (t == 0) {
        out[0] = s_ce[0] / (float)N_MASKS;   // num_masks == 256
        out[1] = s_d[0]  / (float)N_MASKS;
    }
}

// ---------------- launch ----------------
extern "C" void kernel_launch(void* const* d_in, const int* in_sizes, int n_in,
                              void* d_out, int out_size) {
    const float* src = (const float*)d_in[0];   // (256,1,256,256)
    const float* tgt = (const float*)d_in[1];   // (256,1,512,512)
    const float* rc  = (const float*)d_in[2];   // (256,37632,2)
    const float* rf  = (const float*)d_in[3];   // (256,3136,2)
    float* out = (float*)d_out;

    cudaFuncSetAttribute(k_coarse, cudaFuncAttributeMaxDynamicSharedMemorySize,
                         COARSE_SMEM);
    cudaFuncSetAttribute(k_gather, cudaFuncAttributeMaxDynamicSharedMemorySize,
                         GATHER_SMEM);

    void* hist_ptr = nullptr;
    cudaGetSymbolAddress(&hist_ptr, g_hist);
    cudaMemsetAsync(hist_ptr, 0, (size_t)N_MASKS * HIST_BINS * sizeof(unsigned int));

    k_coarse<<<dim3(CSPLIT * 2, N_MASKS), 1024, COARSE_SMEM>>>(src, rc);
    k_select<<<N_MASKS, 1024>>>();
    k_compact<<<dim3(CHUNKS, N_MASKS), 256>>>(src, rc, rf);
    k_gather<<<dim3(SLICES, N_MASKS), 512, GATHER_SMEM>>>(tgt);
    k_final<<<1, 256>>>(out);
}

// round 16
// speedup vs baseline: 2.3502x; 2.3502x over previous
#include <cuda_runtime.h>
#include <math.h>

#define N_MASKS  256
#define S_COARSE 37632
#define K_SEL    9408
#define F_FINE   3136
#define P_TOT    12544
#define SRC_HW   256
#define TGT_HW   512
#define CHUNKS   4
#define S_CHUNK  (S_COARSE / CHUNKS)   // 9408
#define F_CHUNK  (F_FINE / CHUNKS)     // 784

// k_coarse tiling
#define HALF_ROWS   129
#define TILE_FLOATS (HALF_ROWS * SRC_HW)          // 129 KB
#define TILE_BYTES  (TILE_FLOATS * 4)
#define HIST_BINS   2048
#define COARSE_SMEM (TILE_BYTES + HIST_BINS * 4)  // 137 KB
#define CSPLIT      2
#define M_SPLIT     (S_COARSE / CSPLIT)           // 18816

// ---------------- scratch (no cudaMalloc allowed) ----------------
__device__ float        g_logits[N_MASKS * S_COARSE];          // ~38.5 MB
__device__ unsigned int g_hist[N_MASKS * HIST_BINS];           // 2 MB, zeroed per call
__device__ unsigned int g_T22[N_MASKS];
__device__ unsigned int g_below[N_MASKS];
__device__ unsigned int g_eqpref[N_MASKS * CHUNKS];
__device__ float        g_row[N_MASKS * CHUNKS * 4];

// ---- global-memory bilinear (tgt / fine src), matches grid_sample(zeros, ac=False) ----
__device__ __forceinline__ float bilin(const float* __restrict__ img, int HW,
                                       float cx, float cy) {
    float x = cx * (float)HW - 0.5f;
    float y = cy * (float)HW - 0.5f;
    float x0f = floorf(x), y0f = floorf(y);
    int x0 = (int)x0f, y0 = (int)y0f;
    float wx = x - x0f, wy = y - y0f;
    int x1 = x0 + 1, y1 = y0 + 1;
    bool vx0 = (x0 >= 0) & (x0 < HW);
    bool vx1 = (x1 >= 0) & (x1 < HW);
    bool vy0 = (y0 >= 0) & (y0 < HW);
    bool vy1 = (y1 >= 0) & (y1 < HW);
    float v00 = (vx0 && vy0) ? __ldg(img + y0 * HW + x0) : 0.0f;
    float v01 = (vx1 && vy0) ? __ldg(img + y0 * HW + x1) : 0.0f;
    float v10 = (vx0 && vy1) ? __ldg(img + y1 * HW + x0) : 0.0f;
    float v11 = (vx1 && vy1) ? __ldg(img + y1 * HW + x1) : 0.0f;
    return v00 * (1.0f - wx) * (1.0f - wy) + v01 * wx * (1.0f - wy)
         + v10 * (1.0f - wx) * wy          + v11 * wx * wy;
}

// ------- K1: coarse logits via smem-tiled src image + fused pass-1 histogram -------
__global__ __launch_bounds__(1024)
void k_coarse(const float* __restrict__ src, const float* __restrict__ rc) {
    extern __shared__ float sm[];
    unsigned int* hist = (unsigned int*)(sm + TILE_FLOATS);
    int n = blockIdx.y;
    int half  = blockIdx.x & 1;
    int split = blockIdx.x >> 1;
    int base_row = half * 128;
    int nrows = half ? 128 : 129;

    hist[threadIdx.x] = 0;
    hist[threadIdx.x + 1024] = 0;

    const float4* img4 = (const float4*)(src + (size_t)n * (SRC_HW * SRC_HW)
                                         + base_row * SRC_HW);
    int nf4 = nrows * (SRC_HW / 4);
    for (int i = threadIdx.x; i < nf4; i += 1024)
        ((float4*)sm)[i] = img4[i];
    __syncthreads();

    const float4* rc4 = (const float4*)((const float2*)rc
                         + (size_t)n * S_COARSE + split * M_SPLIT);
    float* lrow = g_logits + (size_t)n * S_COARSE + split * M_SPLIT;

    for (int s = threadIdx.x * 4; s < M_SPLIT; s += 4096) {
        float4 a = __ldg(rc4 + (s >> 1));
        float4 b = __ldg(rc4 + (s >> 1) + 1);
        float cxs[4] = {a.x, a.z, b.x, b.z};
        float cys[4] = {a.y, a.w, b.y, b.w};
        #pragma unroll
        for (int p = 0; p < 4; p++) {
            float x = cxs[p] * (float)SRC_HW - 0.5f;
            float y = cys[p] * (float)SRC_HW - 0.5f;
            float x0f = floorf(x), y0f = floorf(y);
            int x0 = (int)x0f, y0 = (int)y0f;
            bool owned = half ? (y0 >= 128) : (y0 <= 127);
            if (!owned) continue;
            float wx = x - x0f, wy = y - y0f;
            int x1 = x0 + 1, y1 = y0 + 1;
            int ly0 = y0 - base_row, ly1 = y1 - base_row;
            bool vx0 = (x0 >= 0) & (x0 < SRC_HW);
            bool vx1 = (x1 >= 0) & (x1 < SRC_HW);
            bool vy0 = (y0 >= 0) & (y0 < SRC_HW);
            bool vy1 = (y1 >= 0) & (y1 < SRC_HW);
            int cx0 = min(max(x0, 0), SRC_HW - 1);
            int cx1 = min(max(x1, 0), SRC_HW - 1);
            int cy0 = min(max(ly0, 0), nrows - 1);
            int cy1 = min(max(ly1, 0), nrows - 1);
            float v00 = (vx0 && vy0) ? sm[cy0 * SRC_HW + cx0] : 0.0f;
            float v01 = (vx1 && vy0) ? sm[cy0 * SRC_HW + cx1] : 0.0f;
            float v10 = (vx0 && vy1) ? sm[cy1 * SRC_HW + cx0] : 0.0f;
            float v11 = (vx1 && vy1) ? sm[cy1 * SRC_HW + cx1] : 0.0f;
            float val = v00 * (1.0f - wx) * (1.0f - wy) + v01 * wx * (1.0f - wy)
                      + v10 * (1.0f - wx) * wy          + v11 * wx * wy;
            lrow[s + p] = val;
            atomicAdd(&hist[(__float_as_uint(val) & 0x7fffffffu) >> 21], 1u);
        }
    }

    __syncthreads();
    unsigned int* gh = g_hist + (size_t)n * HIST_BINS;
    #pragma unroll
    for (int k = 0; k < 2; k++) {
        int i = threadIdx.x + k * 1024;
        unsigned int c = hist[i];
        if (c) atomicAdd(&gh[i], c);
    }
}

// ---- K2: select. Pass 1 from g_hist (no sweep); ONE fused sweep for refine+eqpref ----
__global__ __launch_bounds__(1024)
void k_select() {
    __shared__ unsigned int h2[HIST_BINS * CHUNKS];    // fine x chunk, 32 KB
    __shared__ unsigned int ps[1024];
    __shared__ unsigned int s_b1, s_cum1, s_Tfine, s_below;
    int n = blockIdx.x, t = threadIdx.x;
    const float* row = g_logits + (size_t)n * S_COARSE;

    // ---- pass 1: precomputed coarse histogram (reuse h2[0..2047] as staging) ----
    const unsigned int* gh = g_hist + (size_t)n * HIST_BINS;
    unsigned int hv0 = gh[t], hv1 = gh[t + 1024];
    h2[t] = hv0; h2[t + 1024] = hv1;
    __syncthreads();
    unsigned int my = h2[2 * t] + h2[2 * t + 1];
    unsigned int b0cnt = h2[2 * t], b1cnt = h2[2 * t + 1];
    ps[t] = my;
    __syncthreads();
    for (int off = 1; off < 1024; off <<= 1) {
        unsigned int v = (t >= off) ? ps[t - off] : 0u;
        __syncthreads();
        ps[t] += v;
        __syncthreads();
    }
    {
        unsigned int excl = ps[t] - my;
        if (excl < K_SEL && excl + b0cnt >= K_SEL)               { s_b1 = 2 * t;     s_cum1 = excl; }
        if (excl + b0cnt < K_SEL && excl + b0cnt + b1cnt >= K_SEL){ s_b1 = 2 * t + 1; s_cum1 = excl + b0cnt; }
    }
    __syncthreads();
    unsigned int b1 = s_b1, base = s_cum1;

    // ---- zero fine x chunk histogram ----
    #pragma unroll
    for (int k = 0; k < (HIST_BINS * CHUNKS) / 1024; k++)
        h2[t + k * 1024] = 0;
    __syncthreads();

    // ---- SINGLE sweep: fine histogram binned per chunk ----
    for (int s = t; s < S_COARSE; s += 1024) {
        unsigned int bits = __float_as_uint(row[s]) & 0x7fffffffu;
        if ((bits >> 21) == b1) {
            unsigned int fine = (bits >> 10) & 0x7ffu;
            atomicAdd(&h2[fine * CHUNKS + s / S_CHUNK], 1u);
        }
    }
    __syncthreads();

    // ---- scan fine totals to locate 22-bit threshold ----
    unsigned int t0 = 0, t1 = 0;
    #pragma unroll
    for (int c = 0; c < CHUNKS; c++) {
        t0 += h2[(2 * t)     * CHUNKS + c];
        t1 += h2[(2 * t + 1) * CHUNKS + c];
    }
    my = t0 + t1;
    ps[t] = my;
    __syncthreads();
    for (int off = 1; off < 1024; off <<= 1) {
        unsigned int v = (t >= off) ? ps[t - off] : 0u;
        __syncthreads();
        ps[t] += v;
        __syncthreads();
    }
    {
        unsigned int excl = base + ps[t] - my;
        if (excl < K_SEL && excl + t0 >= K_SEL)            { s_Tfine = 2 * t;     s_below = excl; }
        if (excl + t0 < K_SEL && excl + t0 + t1 >= K_SEL)  { s_Tfine = 2 * t + 1; s_below = excl + t0; }
    }
    __syncthreads();
    if (t == 0) {
        unsigned int Tfine = s_Tfine;
        g_T22[n] = (b1 << 11) | Tfine;
        g_below[n] = s_below;
        unsigned int run = 0;
        #pragma unroll
        for (int c = 0; c < CHUNKS; c++) {
            g_eqpref[n * CHUNKS + c] = run;
            run += h2[Tfine * CHUNKS + c];
        }
    }
}

// ---------------- per-point loss accumulation ----------------
__device__ __forceinline__ void acc_point(float logit, float label,
                                          float& a_bce, float& a_pl, float& a_p, float& a_l) {
    float e = expf(-fabsf(logit));
    float prob = (logit >= 0.0f) ? 1.0f / (1.0f + e) : e / (1.0f + e);
    float bce  = fmaxf(logit, 0.0f) - logit * label + log1pf(e);
    a_bce += bce;
    a_pl  += prob * label;
    a_p   += prob;
    a_l   += label;
}

// ---- K3: fused deterministic select + loss — EXACT proven version ----
__global__ __launch_bounds__(256)
void k_loss(const float* __restrict__ src, const float* __restrict__ tgt,
            const float* __restrict__ rc, const float* __restrict__ rf) {
    int chunk = blockIdx.x, n = blockIdx.y, t = threadIdx.x;
    int lane = t & 31, wid = t >> 5;
    const float* simg = src + (size_t)n * (SRC_HW * SRC_HW);
    const float* timg = tgt + (size_t)n * (TGT_HW * TGT_HW);
    unsigned int T = g_T22[n];
    unsigned int r = K_SEL - g_below[n];

    __shared__ unsigned int warpcnt[8];
    __shared__ unsigned int s_run;
    __shared__ float red[8];
    if (t == 0) s_run = g_eqpref[n * CHUNKS + chunk];
    __syncthreads();

    float a_bce = 0.f, a_pl = 0.f, a_p = 0.f, a_l = 0.f;

    const float*  lrow = g_logits + (size_t)n * S_COARSE;
    const float2* rc2  = (const float2*)rc + (size_t)n * S_COARSE;

    int s_begin = chunk * S_CHUNK, s_end = s_begin + S_CHUNK;
    for (int base = s_begin; base < s_end; base += 256) {
        int s = base + t;
        bool valid = s < s_end;
        float logit = 0.0f;
        unsigned int b22 = 0xffffffffu;
        if (valid) {
            logit = lrow[s];
            b22 = (__float_as_uint(logit) & 0x7fffffffu) >> 10;
        }
        bool lt = valid && (b22 < T);
        bool eq = valid && (b22 == T);
        unsigned int bal = __ballot_sync(0xffffffffu, eq);
        if (lane == 0) warpcnt[wid] = (unsigned int)__popc(bal);
        __syncthreads();
        unsigned int wbase = 0;
        #pragma unroll
        for (int w = 0; w < 8; w++) wbase += (w < wid) ? warpcnt[w] : 0u;
        unsigned int rank = s_run + wbase + (unsigned int)__popc(bal & ((1u << lane) - 1u));
        bool sel = lt || (eq && rank < r);
        __syncthreads();
        if (t == 0) {
            unsigned int tot = 0;
            #pragma unroll
            for (int w = 0; w < 8; w++) tot += warpcnt[w];
            s_run += tot;
        }
        if (sel) {
            float2 c = rc2[s];
            float label = bilin(timg, TGT_HW, c.x, c.y);
            acc_point(logit, label, a_bce, a_pl, a_p, a_l);
        }
        __syncthreads();
    }

    const float2* rf2 = (const float2*)rf + (size_t)n * F_FINE;
    int f_begin = chunk * F_CHUNK, f_end = f_begin + F_CHUNK;
    for (int f = f_begin + t; f < f_end; f += 256) {
        float2 c = rf2[f];
        float logit = bilin(simg, SRC_HW, c.x, c.y);
        float label = bilin(timg, TGT_HW, c.x, c.y);
        acc_point(logit, label, a_bce, a_pl, a_p, a_l);
    }

    float vals[4] = {a_bce, a_pl, a_p, a_l};
    #pragma unroll
    for (int k = 0; k < 4; k++) {
        float v = vals[k];
        #pragma unroll
        for (int o = 16; o > 0; o >>= 1) v += __shfl_down_sync(0xffffffffu, v, o);
        if (lane == 0) red[wid] = v;
        __syncthreads();
        if (t == 0) {
            float tot = 0.f;
            #pragma unroll
            for (int w = 0; w < 8; w++) tot += red[w];
            g_row[(n * CHUNKS + chunk) * 4 + k] = tot;
        }
        __syncthreads();
    }
}

// ---------------- K4: final reduction -> 2 outputs ----------------
__global__ __launch_bounds__(256)
void k_final(float* __restrict__ out) {
    __shared__ float s_ce[256];
    __shared__ float s_d[256];
    int t = threadIdx.x;           // t = row
    float bce = 0.f, pl = 0.f, p = 0.f, l = 0.f;
    #pragma unroll
    for (int c = 0; c < CHUNKS; c++) {
        const float* g = &g_row[(t * CHUNKS + c) * 4];
        bce += g[0]; pl += g[1]; p += g[2]; l += g[3];
    }
    s_ce[t] = bce / (float)P_TOT;
    s_d[t]  = 1.0f - (2.0f * pl + 1.0f) / (p + l + 1.0f);
    __syncthreads();
    for (int o = 128; o > 0; o >>= 1) {
        if (t < o) { s_ce[t] += s_ce[t + o]; s_d[t] += s_d[t + o]; }
        __syncthreads();
    }
    if (t == 0) {
        out[0] = s_ce[0] / (float)N_MASKS;   // num_masks == 256
        out[1] = s_d[0]  / (float)N_MASKS;
    }
}

// ---------------- launch ----------------
extern "C" void kernel_launch(void* const* d_in, const int* in_sizes, int n_in,
                              void* d_out, int out_size) {
    const float* src = (const float*)d_in[0];   // (256,1,256,256)
    const float* tgt = (const float*)d_in[1];   // (256,1,512,512)
    const float* rc  = (const float*)d_in[2];   // (256,37632,2)
    const float* rf  = (const float*)d_in[3];   // (256,3136,2)
    float* out = (float*)d_out;

    cudaFuncSetAttribute(k_coarse, cudaFuncAttributeMaxDynamicSharedMemorySize,
                         COARSE_SMEM);

    void* hist_ptr = nullptr;
    cudaGetSymbolAddress(&hist_ptr, g_hist);
    cudaMemsetAsync(hist_ptr, 0, (size_t)N_MASKS * HIST_BINS * sizeof(unsigned int));

    k_coarse<<<dim3(CSPLIT * 2, N_MASKS), 1024, COARSE_SMEM>>>(src, rc);
    k_select<<<N_MASKS, 1024>>>();
    k_loss<<<dim3(CHUNKS, N_MASKS), 256>>>(src, tgt, rc, rf);
    k_final<<<1, 256>>>(out);
}

// round 17
// speedup vs baseline: 2.3675x; 1.0073x over previous
#include <cuda_runtime.h>
#include <math.h>

#define N_MASKS  256
#define S_COARSE 37632
#define K_SEL    9408
#define F_FINE   3136
#define P_TOT    12544
#define SRC_HW   256
#define TGT_HW   512
#define CHUNKS   4
#define S_CHUNK  (S_COARSE / CHUNKS)   // 9408
#define F_CHUNK  (F_FINE / CHUNKS)     // 784

// k_coarse tiling: each block owns one y-half of the image, scans ALL coords
#define HALF_ROWS   129
#define TILE_FLOATS (HALF_ROWS * SRC_HW)          // 129 KB
#define TILE_BYTES  (TILE_FLOATS * 4)
#define HIST_BINS   2048
#define COARSE_SMEM (TILE_BYTES + HIST_BINS * 4)  // 137 KB

// ---------------- scratch (no cudaMalloc allowed) ----------------
__device__ float        g_logits[N_MASKS * S_COARSE];          // ~38.5 MB
__device__ unsigned int g_hist[N_MASKS * HIST_BINS];           // 2 MB, zeroed per call
__device__ unsigned int g_T22[N_MASKS];
__device__ unsigned int g_below[N_MASKS];
__device__ unsigned int g_eqpref[N_MASKS * CHUNKS];
__device__ float        g_row[N_MASKS * CHUNKS * 4];

// ---- global-memory bilinear (tgt / fine src), matches grid_sample(zeros, ac=False) ----
__device__ __forceinline__ float bilin(const float* __restrict__ img, int HW,
                                       float cx, float cy) {
    float x = cx * (float)HW - 0.5f;
    float y = cy * (float)HW - 0.5f;
    float x0f = floorf(x), y0f = floorf(y);
    int x0 = (int)x0f, y0 = (int)y0f;
    float wx = x - x0f, wy = y - y0f;
    int x1 = x0 + 1, y1 = y0 + 1;
    bool vx0 = (x0 >= 0) & (x0 < HW);
    bool vx1 = (x1 >= 0) & (x1 < HW);
    bool vy0 = (y0 >= 0) & (y0 < HW);
    bool vy1 = (y1 >= 0) & (y1 < HW);
    float v00 = (vx0 && vy0) ? __ldg(img + y0 * HW + x0) : 0.0f;
    float v01 = (vx1 && vy0) ? __ldg(img + y0 * HW + x1) : 0.0f;
    float v10 = (vx0 && vy1) ? __ldg(img + y1 * HW + x0) : 0.0f;
    float v11 = (vx1 && vy1) ? __ldg(img + y1 * HW + x1) : 0.0f;
    return v00 * (1.0f - wx) * (1.0f - wy) + v01 * wx * (1.0f - wy)
         + v10 * (1.0f - wx) * wy          + v11 * wx * wy;
}

// ------- K1: coarse logits via smem-tiled src image + fused pass-1 histogram -------
// grid (2, N_MASKS): blockIdx.x = half. Each half's tile filled ONCE; block scans
// the full coord row and processes only owned points (disjoint exhaustive split).
__global__ __launch_bounds__(1024)
void k_coarse(const float* __restrict__ src, const float* __restrict__ rc) {
    extern __shared__ float sm[];
    unsigned int* hist = (unsigned int*)(sm + TILE_FLOATS);
    int n = blockIdx.y;
    int half = blockIdx.x;
    int base_row = half * 128;
    int nrows = half ? 128 : 129;

    hist[threadIdx.x] = 0;
    hist[threadIdx.x + 1024] = 0;

    const float4* img4 = (const float4*)(src + (size_t)n * (SRC_HW * SRC_HW)
                                         + base_row * SRC_HW);
    int nf4 = nrows * (SRC_HW / 4);
    for (int i = threadIdx.x; i < nf4; i += 1024)
        ((float4*)sm)[i] = img4[i];
    __syncthreads();

    const float4* rc4 = (const float4*)((const float2*)rc + (size_t)n * S_COARSE);
    float* lrow = g_logits + (size_t)n * S_COARSE;

    for (int s = threadIdx.x * 4; s < S_COARSE; s += 4096) {
        float4 a = __ldg(rc4 + (s >> 1));
        float4 b = __ldg(rc4 + (s >> 1) + 1);
        float cxs[4] = {a.x, a.z, b.x, b.z};
        float cys[4] = {a.y, a.w, b.y, b.w};
        #pragma unroll
        for (int p = 0; p < 4; p++) {
            float x = cxs[p] * (float)SRC_HW - 0.5f;
            float y = cys[p] * (float)SRC_HW - 0.5f;
            float x0f = floorf(x), y0f = floorf(y);
            int x0 = (int)x0f, y0 = (int)y0f;
            bool owned = half ? (y0 >= 128) : (y0 <= 127);
            if (!owned) continue;
            float wx = x - x0f, wy = y - y0f;
            int x1 = x0 + 1, y1 = y0 + 1;
            int ly0 = y0 - base_row, ly1 = y1 - base_row;
            bool vx0 = (x0 >= 0) & (x0 < SRC_HW);
            bool vx1 = (x1 >= 0) & (x1 < SRC_HW);
            bool vy0 = (y0 >= 0) & (y0 < SRC_HW);
            bool vy1 = (y1 >= 0) & (y1 < SRC_HW);
            int cx0 = min(max(x0, 0), SRC_HW - 1);
            int cx1 = min(max(x1, 0), SRC_HW - 1);
            int cy0 = min(max(ly0, 0), nrows - 1);
            int cy1 = min(max(ly1, 0), nrows - 1);
            float v00 = (vx0 && vy0) ? sm[cy0 * SRC_HW + cx0] : 0.0f;
            float v01 = (vx1 && vy0) ? sm[cy0 * SRC_HW + cx1] : 0.0f;
            float v10 = (vx0 && vy1) ? sm[cy1 * SRC_HW + cx0] : 0.0f;
            float v11 = (vx1 && vy1) ? sm[cy1 * SRC_HW + cx1] : 0.0f;
            float val = v00 * (1.0f - wx) * (1.0f - wy) + v01 * wx * (1.0f - wy)
                      + v10 * (1.0f - wx) * wy          + v11 * wx * wy;
            lrow[s + p] = val;
            atomicAdd(&hist[(__float_as_uint(val) & 0x7fffffffu) >> 21], 1u);
        }
    }

    __syncthreads();
    unsigned int* gh = g_hist + (size_t)n * HIST_BINS;
    #pragma unroll
    for (int k = 0; k < 2; k++) {
        int i = threadIdx.x + k * 1024;
        unsigned int c = hist[i];
        if (c) atomicAdd(&gh[i], c);
    }
}

// ---- K2: select. Pass 1 from g_hist (no sweep); ONE fused sweep for refine+eqpref ----
__global__ __launch_bounds__(1024)
void k_select() {
    __shared__ unsigned int h2[HIST_BINS * CHUNKS];    // fine x chunk, 32 KB
    __shared__ unsigned int ps[1024];
    __shared__ unsigned int s_b1, s_cum1, s_Tfine, s_below;
    int n = blockIdx.x, t = threadIdx.x;
    const float* row = g_logits + (size_t)n * S_COARSE;

    // ---- pass 1: precomputed coarse histogram (reuse h2[0..2047] as staging) ----
    const unsigned int* gh = g_hist + (size_t)n * HIST_BINS;
    unsigned int hv0 = gh[t], hv1 = gh[t + 1024];
    h2[t] = hv0; h2[t + 1024] = hv1;
    __syncthreads();
    unsigned int my = h2[2 * t] + h2[2 * t + 1];
    unsigned int b0cnt = h2[2 * t], b1cnt = h2[2 * t + 1];
    ps[t] = my;
    __syncthreads();
    for (int off = 1; off < 1024; off <<= 1) {
        unsigned int v = (t >= off) ? ps[t - off] : 0u;
        __syncthreads();
        ps[t] += v;
        __syncthreads();
    }
    {
        unsigned int excl = ps[t] - my;
        if (excl < K_SEL && excl + b0cnt >= K_SEL)                { s_b1 = 2 * t;     s_cum1 = excl; }
        if (excl + b0cnt < K_SEL && excl + b0cnt + b1cnt >= K_SEL){ s_b1 = 2 * t + 1; s_cum1 = excl + b0cnt; }
    }
    __syncthreads();
    unsigned int b1 = s_b1, base = s_cum1;

    // ---- zero fine x chunk histogram ----
    #pragma unroll
    for (int k = 0; k < (HIST_BINS * CHUNKS) / 1024; k++)
        h2[t + k * 1024] = 0;
    __syncthreads();

    // ---- SINGLE sweep: fine histogram binned per chunk ----
    for (int s = t; s < S_COARSE; s += 1024) {
        unsigned int bits = __float_as_uint(row[s]) & 0x7fffffffu;
        if ((bits >> 21) == b1) {
            unsigned int fine = (bits >> 10) & 0x7ffu;
            atomicAdd(&h2[fine * CHUNKS + s / S_CHUNK], 1u);
        }
    }
    __syncthreads();

    // ---- scan fine totals to locate 22-bit threshold ----
    unsigned int t0 = 0, t1 = 0;
    #pragma unroll
    for (int c = 0; c < CHUNKS; c++) {
        t0 += h2[(2 * t)     * CHUNKS + c];
        t1 += h2[(2 * t + 1) * CHUNKS + c];
    }
    my = t0 + t1;
    ps[t] = my;
    __syncthreads();
    for (int off = 1; off < 1024; off <<= 1) {
        unsigned int v = (t >= off) ? ps[t - off] : 0u;
        __syncthreads();
        ps[t] += v;
        __syncthreads();
    }
    {
        unsigned int excl = base + ps[t] - my;
        if (excl < K_SEL && excl + t0 >= K_SEL)            { s_Tfine = 2 * t;     s_below = excl; }
        if (excl + t0 < K_SEL && excl + t0 + t1 >= K_SEL)  { s_Tfine = 2 * t + 1; s_below = excl + t0; }
    }
    __syncthreads();
    if (t == 0) {
        unsigned int Tfine = s_Tfine;
        g_T22[n] = (b1 << 11) | Tfine;
        g_below[n] = s_below;
        unsigned int run = 0;
        #pragma unroll
        for (int c = 0; c < CHUNKS; c++) {
            g_eqpref[n * CHUNKS + c] = run;
            run += h2[Tfine * CHUNKS + c];
        }
    }
}

// ---------------- per-point loss accumulation ----------------
__device__ __forceinline__ void acc_point(float logit, float label,
                                          float& a_bce, float& a_pl, float& a_p, float& a_l) {
    float e = expf(-fabsf(logit));
    float prob = (logit >= 0.0f) ? 1.0f / (1.0f + e) : e / (1.0f + e);
    float bce  = fmaxf(logit, 0.0f) - logit * label + log1pf(e);
    a_bce += bce;
    a_pl  += prob * label;
    a_p   += prob;
    a_l   += label;
}

// ---- K3: fused deterministic select + loss — EXACT proven version ----
__global__ __launch_bounds__(256)
void k_loss(const float* __restrict__ src, const float* __restrict__ tgt,
            const float* __restrict__ rc, const float* __restrict__ rf) {
    int chunk = blockIdx.x, n = blockIdx.y, t = threadIdx.x;
    int lane = t & 31, wid = t >> 5;
    const float* simg = src + (size_t)n * (SRC_HW * SRC_HW);
    const float* timg = tgt + (size_t)n * (TGT_HW * TGT_HW);
    unsigned int T = g_T22[n];
    unsigned int r = K_SEL - g_below[n];

    __shared__ unsigned int warpcnt[8];
    __shared__ unsigned int s_run;
    __shared__ float red[8];
    if (t == 0) s_run = g_eqpref[n * CHUNKS + chunk];
    __syncthreads();

    float a_bce = 0.f, a_pl = 0.f, a_p = 0.f, a_l = 0.f;

    const float*  lrow = g_logits + (size_t)n * S_COARSE;
    const float2* rc2  = (const float2*)rc + (size_t)n * S_COARSE;

    int s_begin = chunk * S_CHUNK, s_end = s_begin + S_CHUNK;
    for (int base = s_begin; base < s_end; base += 256) {
        int s = base + t;
        bool valid = s < s_end;
        float logit = 0.0f;
        unsigned int b22 = 0xffffffffu;
        if (valid) {
            logit = lrow[s];
            b22 = (__float_as_uint(logit) & 0x7fffffffu) >> 10;
        }
        bool lt = valid && (b22 < T);
        bool eq = valid && (b22 == T);
        unsigned int bal = __ballot_sync(0xffffffffu, eq);
        if (lane == 0) warpcnt[wid] = (unsigned int)__popc(bal);
        __syncthreads();
        unsigned int wbase = 0;
        #pragma unroll
        for (int w = 0; w < 8; w++) wbase += (w < wid) ? warpcnt[w] : 0u;
        unsigned int rank = s_run + wbase + (unsigned int)__popc(bal & ((1u << lane) - 1u));
        bool sel = lt || (eq && rank < r);
        __syncthreads();
        if (t == 0) {
            unsigned int tot = 0;
            #pragma unroll
            for (int w = 0; w < 8; w++) tot += warpcnt[w];
            s_run += tot;
        }
        if (sel) {
            float2 c = rc2[s];
            float label = bilin(timg, TGT_HW, c.x, c.y);
            acc_point(logit, label, a_bce, a_pl, a_p, a_l);
        }
        __syncthreads();
    }

    const float2* rf2 = (const float2*)rf + (size_t)n * F_FINE;
    int f_begin = chunk * F_CHUNK, f_end = f_begin + F_CHUNK;
    for (int f = f_begin + t; f < f_end; f += 256) {
        float2 c = rf2[f];
        float logit = bilin(simg, SRC_HW, c.x, c.y);
        float label = bilin(timg, TGT_HW, c.x, c.y);
        acc_point(logit, label, a_bce, a_pl, a_p, a_l);
    }

    float vals[4] = {a_bce, a_pl, a_p, a_l};
    #pragma unroll
    for (int k = 0; k < 4; k++) {
        float v = vals[k];
        #pragma unroll
        for (int o = 16; o > 0; o >>= 1) v += __shfl_down_sync(0xffffffffu, v, o);
        if (lane == 0) red[wid] = v;
        __syncthreads();
        if (t == 0) {
            float tot = 0.f;
            #pragma unroll
            for (int w = 0; w < 8; w++) tot += red[w];
            g_row[(n * CHUNKS + chunk) * 4 + k] = tot;
        }
        __syncthreads();
    }
}

// ---------------- K4: final reduction -> 2 outputs ----------------
__global__ __launch_bounds__(256)
void k_final(float* __restrict__ out) {
    __shared__ float s_ce[256];
    __shared__ float s_d[256];
    int t = threadIdx.x;           // t = row
    float bce = 0.f, pl = 0.f, p = 0.f, l = 0.f;
    #pragma unroll
    for (int c = 0; c < CHUNKS; c++) {
        const float* g = &g_row[(t * CHUNKS + c) * 4];
        bce += g[0]; pl += g[1]; p += g[2]; l += g[3];
    }
    s_ce[t] = bce / (float)P_TOT;
    s_d[t]  = 1.0f - (2.0f * pl + 1.0f) / (p + l + 1.0f);
    __syncthreads();
    for (int o = 128; o > 0; o >>= 1) {
        if (t < o) { s_ce[t] += s_ce[t + o]; s_d[t] += s_d[t + o]; }
        __syncthreads();
    }
    if (t == 0) {
        out[0] = s_ce[0] / (float)N_MASKS;   // num_masks == 256
        out[1] = s_d[0]  / (float)N_MASKS;
    }
}

// ---------------- launch ----------------
extern "C" void kernel_launch(void* const* d_in, const int* in_sizes, int n_in,
                              void* d_out, int out_size) {
    const float* src = (const float*)d_in[0];   // (256,1,256,256)
    const float* tgt = (const float*)d_in[1];   // (256,1,512,512)
    const float* rc  = (const float*)d_in[2];   // (256,37632,2)
    const float* rf  = (const float*)d_in[3];   // (256,3136,2)
    float* out = (float*)d_out;

    cudaFuncSetAttribute(k_coarse, cudaFuncAttributeMaxDynamicSharedMemorySize,
                         COARSE_SMEM);

    void* hist_ptr = nullptr;
    cudaGetSymbolAddress(&hist_ptr, g_hist);
    cudaMemsetAsync(hist_ptr, 0, (size_t)N_MASKS * HIST_BINS * sizeof(unsigned int));

    k_coarse<<<dim3(2, N_MASKS), 1024, COARSE_SMEM>>>(src, rc);
    k_select<<<N_MASKS, 1024>>>();
    k_loss<<<dim3(CHUNKS, N_MASKS), 256>>>(src, tgt, rc, rf);
    k_final<<<1, 256>>>(out);
}